// round 1
// baseline (speedup 1.0000x reference)
#include <cuda_runtime.h>
#include <float.h>

// Chamfer distance loss: B=4, N=M=4096, D=3.
// dist(p,g) = ||p||^2 + ||g||^2 - 2 p.g
// Inner loop computes d' = ||g||^2 + (-2p).g  (3 FFMA per pair, chain seeded
// with the precomputed ||g||^2 stored in the .w of the shared float4).
// ||p||^2 is a per-thread constant -> added once after the min.

#define BATCH 4
#define NPTS  4096
#define TPB   128
#define CHUNKS (NPTS / TPB)              // 32 blocks per (batch, dir)
#define NPARTIALS (CHUNKS * BATCH * 2)   // 256

__device__ float g_partials[NPARTIALS];

__global__ void __launch_bounds__(TPB) chamfer_kernel(
    const float* __restrict__ recon,
    const float* __restrict__ gt)
{
    extern __shared__ float4 sdst[];   // 4096 x float4 = 64 KB

    const int bx  = blockIdx.x;   // src chunk
    const int b   = blockIdx.y;   // batch
    const int dir = blockIdx.z;   // 0: recon->gt, 1: gt->recon
    const int tid = threadIdx.x;

    const float* src = (dir == 0) ? recon : gt;
    const float* dst = (dir == 0) ? gt : recon;
    const float* dstb = dst + (size_t)b * NPTS * 3;

    // Cache the full opposite point set (+ squared norm) in shared memory.
    for (int j = tid; j < NPTS; j += TPB) {
        float x = dstb[3 * j + 0];
        float y = dstb[3 * j + 1];
        float z = dstb[3 * j + 2];
        sdst[j] = make_float4(x, y, z, fmaf(x, x, fmaf(y, y, z * z)));
    }
    __syncthreads();

    // Each thread owns one source point.
    const int i = bx * TPB + tid;
    const float* sp = src + ((size_t)b * NPTS + i) * 3;
    const float px = sp[0], py = sp[1], pz = sp[2];
    const float qx = -2.0f * px, qy = -2.0f * py, qz = -2.0f * pz;
    const float np = fmaf(px, px, fmaf(py, py, pz * pz));

    float m0 = FLT_MAX, m1 = FLT_MAX, m2 = FLT_MAX, m3 = FLT_MAX;

    #pragma unroll 2
    for (int j = 0; j < NPTS; j += 8) {
        float4 g0 = sdst[j + 0];
        float4 g1 = sdst[j + 1];
        float4 g2 = sdst[j + 2];
        float4 g3 = sdst[j + 3];
        float4 g4 = sdst[j + 4];
        float4 g5 = sdst[j + 5];
        float4 g6 = sdst[j + 6];
        float4 g7 = sdst[j + 7];

        float d0 = fmaf(qx, g0.x, fmaf(qy, g0.y, fmaf(qz, g0.z, g0.w)));
        float d1 = fmaf(qx, g1.x, fmaf(qy, g1.y, fmaf(qz, g1.z, g1.w)));
        float d2 = fmaf(qx, g2.x, fmaf(qy, g2.y, fmaf(qz, g2.z, g2.w)));
        float d3 = fmaf(qx, g3.x, fmaf(qy, g3.y, fmaf(qz, g3.z, g3.w)));
        float d4 = fmaf(qx, g4.x, fmaf(qy, g4.y, fmaf(qz, g4.z, g4.w)));
        float d5 = fmaf(qx, g5.x, fmaf(qy, g5.y, fmaf(qz, g5.z, g5.w)));
        float d6 = fmaf(qx, g6.x, fmaf(qy, g6.y, fmaf(qz, g6.z, g6.w)));
        float d7 = fmaf(qx, g7.x, fmaf(qy, g7.y, fmaf(qz, g7.z, g7.w)));

        m0 = fminf(m0, d0);
        m1 = fminf(m1, d1);
        m2 = fminf(m2, d2);
        m3 = fminf(m3, d3);
        m0 = fminf(m0, d4);
        m1 = fminf(m1, d5);
        m2 = fminf(m2, d6);
        m3 = fminf(m3, d7);
    }

    float m = fminf(fminf(m0, m1), fminf(m2, m3)) + np;

    // Deterministic block sum (fixed-order tree).
    __syncthreads();   // shared buffer reuse
    float* sred = (float*)sdst;
    sred[tid] = m;
    __syncthreads();
    #pragma unroll
    for (int s = TPB / 2; s > 0; s >>= 1) {
        if (tid < s) sred[tid] += sred[tid + s];
        __syncthreads();
    }
    if (tid == 0)
        g_partials[bx + CHUNKS * (b + BATCH * dir)] = sred[0];
}

__global__ void __launch_bounds__(NPARTIALS) finalize_kernel(float* out)
{
    __shared__ float s[NPARTIALS];
    const int tid = threadIdx.x;
    s[tid] = g_partials[tid];
    __syncthreads();
    #pragma unroll
    for (int st = NPARTIALS / 2; st > 0; st >>= 1) {
        if (tid < st) s[tid] += s[tid + st];
        __syncthreads();
    }
    if (tid == 0)
        out[0] = s[0] / (float)(2 * BATCH * NPTS);  // (mean1 + mean2) / 2
}

extern "C" void kernel_launch(void* const* d_in, const int* in_sizes, int n_in,
                              void* d_out, int out_size)
{
    const float* recon = (const float*)d_in[0];
    const float* gt    = (const float*)d_in[1];
    float* out = (float*)d_out;

    const int smem = NPTS * (int)sizeof(float4);  // 64 KB
    cudaFuncSetAttribute(chamfer_kernel,
                         cudaFuncAttributeMaxDynamicSharedMemorySize, smem);

    dim3 grid(CHUNKS, BATCH, 2);
    chamfer_kernel<<<grid, TPB, smem>>>(recon, gt);
    finalize_kernel<<<1, NPARTIALS>>>(out);
}